// round 1
// baseline (speedup 1.0000x reference)
#include <cuda_runtime.h>

#define T_DIM 128
#define B_DIM 512
#define D_IN  768
#define TB    (T_DIM * B_DIM)   // 65536

// ---------------- scratch (device globals; no allocations) ----------------
__device__ float g_G [TB * 64];   // bi-LSTM input-proj gates (fwd 0..31, bwd 32..63)
__device__ float g_h [TB * 16];   // concat bi-LSTM hidden  [t][b][16]
__device__ float g_Gp[TB * 64];   // ptr-LSTM input-proj gates
__device__ float g_z [TB * 16];   // ptr-LSTM hidden
__device__ float g_rs[TB];        // 1 / column-softmax-denominator, [t][c]

// ---------------- fast activations ----------------
__device__ __forceinline__ float ex2f(float x) { float y; asm("ex2.approx.ftz.f32 %0, %1;" : "=f"(y) : "f"(x)); return y; }
__device__ __forceinline__ float rcpf(float x) { float y; asm("rcp.approx.ftz.f32 %0, %1;" : "=f"(y) : "f"(x)); return y; }
__device__ __forceinline__ float sigmoidf_(float x) { return rcpf(1.f + ex2f(-1.4426950408889634f * x)); }
__device__ __forceinline__ float tanhf_(float x)    { return 2.f * sigmoidf_(2.f * x) - 1.f; }

// =====================================================================
// Kernel 1: input GEMM  G[m][n] = X[m][:] . W2[n][:] + bias[n]
//   M=65536, N=64 (rows 0..31 = Wih_f, 32..63 = Wih_b), K=768
// =====================================================================
__global__ __launch_bounds__(256) void k_gemm_in(
    const float* __restrict__ X,
    const float* __restrict__ Wf, const float* __restrict__ Wb,
    const float* __restrict__ bihf, const float* __restrict__ bhhf,
    const float* __restrict__ bihb, const float* __restrict__ bhhb)
{
    __shared__ __align__(16) float As[128][32];
    __shared__ __align__(16) float Bs[32][68];
    int tid = threadIdx.x;
    int m0  = blockIdx.x * 128;
    int tx  = tid & 15, ty = tid >> 4;   // tx: 4-col group, ty: 8-row group
    float acc[8][4];
#pragma unroll
    for (int r = 0; r < 8; ++r)
#pragma unroll
        for (int c = 0; c < 4; ++c) acc[r][c] = 0.f;

    for (int k0 = 0; k0 < D_IN; k0 += 32) {
#pragma unroll
        for (int i = 0; i < 4; ++i) {               // A tile: 1024 float4
            int idx = tid + i * 256;
            int m = idx >> 3, kk = (idx & 7) << 2;
            float4 v = *(const float4*)(X + (size_t)(m0 + m) * D_IN + k0 + kk);
            *(float4*)&As[m][kk] = v;
        }
#pragma unroll
        for (int i = 0; i < 2; ++i) {               // B tile: 512 float4
            int idx = tid + i * 256;
            int n = idx >> 3, kk = (idx & 7) << 2;
            const float* src = (n < 32) ? (Wf + (size_t)n * D_IN) : (Wb + (size_t)(n - 32) * D_IN);
            float4 v = *(const float4*)(src + k0 + kk);
            Bs[kk + 0][n] = v.x; Bs[kk + 1][n] = v.y; Bs[kk + 2][n] = v.z; Bs[kk + 3][n] = v.w;
        }
        __syncthreads();
#pragma unroll
        for (int k = 0; k < 32; ++k) {
            float a[8];
#pragma unroll
            for (int r = 0; r < 8; ++r) a[r] = As[ty * 8 + r][k];
            float4 bv = *(float4*)&Bs[k][tx * 4];
            float bb[4] = {bv.x, bv.y, bv.z, bv.w};
#pragma unroll
            for (int r = 0; r < 8; ++r)
#pragma unroll
                for (int c = 0; c < 4; ++c) acc[r][c] += a[r] * bb[c];
        }
        __syncthreads();
    }
    float bias[4];
#pragma unroll
    for (int c = 0; c < 4; ++c) {
        int n = tx * 4 + c;
        bias[c] = (n < 32) ? (bihf[n] + bhhf[n]) : (bihb[n - 32] + bhhb[n - 32]);
    }
#pragma unroll
    for (int r = 0; r < 8; ++r) {
        int m = m0 + ty * 8 + r;
        float4 v = make_float4(acc[r][0] + bias[0], acc[r][1] + bias[1],
                               acc[r][2] + bias[2], acc[r][3] + bias[3]);
        *(float4*)(g_G + (size_t)m * 64 + tx * 4) = v;
    }
}

// =====================================================================
// Kernel 2: bi-LSTM scan. 4 lanes per (item, direction); lane r owns
// gate group r (i/f/g/o), Whh slice (8x8) in registers; h,c replicated.
// =====================================================================
__global__ __launch_bounds__(128) void k_bilstm(const float* __restrict__ WhhF,
                                                const float* __restrict__ WhhB)
{
    int dir = blockIdx.y;
    int tid = threadIdx.x;
    int r = tid & 3, g = tid >> 2;          // g < 32
    int b = blockIdx.x * 32 + g;
    const float* Whh = dir ? WhhB : WhhF;
    float w[8][8];
#pragma unroll
    for (int j = 0; j < 8; ++j)
#pragma unroll
        for (int k = 0; k < 8; ++k) w[j][k] = Whh[(8 * r + j) * 8 + k];
    float h[8], c[8];
#pragma unroll
    for (int j = 0; j < 8; ++j) { h[j] = 0.f; c[j] = 0.f; }
    float s2  = (r == 2) ? 2.f : 1.f;      // gate group 2 = g-gate -> tanh
    float off = s2 - 1.f;
    int base = (tid & 31) & ~3;

    for (int s = 0; s < 128; ++s) {
        int t = dir ? (127 - s) : s;
        const float* gp = g_G + ((size_t)t * B_DIM + b) * 64 + dir * 32 + r * 8;
        float4 p0 = *(const float4*)gp;
        float4 p1 = *(const float4*)(gp + 4);
        float gv[8] = {p0.x, p0.y, p0.z, p0.w, p1.x, p1.y, p1.z, p1.w};
        float act[8];
#pragma unroll
        for (int j = 0; j < 8; ++j) {
            float x = gv[j];
#pragma unroll
            for (int k = 0; k < 8; ++k) x += h[k] * w[j][k];
            act[j] = s2 * sigmoidf_(s2 * x) - off;   // sigmoid or tanh
        }
#pragma unroll
        for (int j = 0; j < 8; ++j) {
            float iv = __shfl_sync(0xffffffffu, act[j], base + 0);
            float fv = __shfl_sync(0xffffffffu, act[j], base + 1);
            float gg = __shfl_sync(0xffffffffu, act[j], base + 2);
            float ov = __shfl_sync(0xffffffffu, act[j], base + 3);
            c[j] = fv * c[j] + iv * gg;
            h[j] = ov * tanhf_(c[j]);
        }
        if (r == 0) {
            float* out = g_h + ((size_t)t * B_DIM + b) * 16 + dir * 8;
            *(float4*)out       = make_float4(h[0], h[1], h[2], h[3]);
            *(float4*)(out + 4) = make_float4(h[4], h[5], h[6], h[7]);
        }
    }
}

// =====================================================================
// Kernel 3: ptr-LSTM input projection  Gp[m][n] = h[m][:] . Wih_p[n][:] + bias
// =====================================================================
__global__ __launch_bounds__(256) void k_gp(const float* __restrict__ Wihp,
                                            const float* __restrict__ bihp,
                                            const float* __restrict__ bhhp)
{
    __shared__ float Wp[64][17];
    __shared__ float bs[64];
    int tid = threadIdx.x;
    if (tid < 64) bs[tid] = bihp[tid] + bhhp[tid];
    for (int i = tid; i < 1024; i += 256) Wp[i >> 4][i & 15] = Wihp[i];
    __syncthreads();
    int n  = tid & 63, mi = tid >> 6;
    int m  = blockIdx.x * 4 + mi;
    const float* hr = g_h + (size_t)m * 16;
    float4 h0 = *(const float4*)hr,       h1 = *(const float4*)(hr + 4);
    float4 h2 = *(const float4*)(hr + 8), h3 = *(const float4*)(hr + 12);
    float hv[16] = {h0.x, h0.y, h0.z, h0.w, h1.x, h1.y, h1.z, h1.w,
                    h2.x, h2.y, h2.z, h2.w, h3.x, h3.y, h3.z, h3.w};
    float acc = bs[n];
#pragma unroll
    for (int k = 0; k < 16; ++k) acc += hv[k] * Wp[n][k];
    g_Gp[(size_t)m * 64 + n] = acc;
}

// =====================================================================
// Kernel 4: ptr-LSTM scan. 8 lanes/item, lane r owns gates [8r,8r+8),
// Whh_p slice (8x16) in registers; gate values exchanged via smem.
// =====================================================================
__global__ __launch_bounds__(128) void k_ptr(const float* __restrict__ Whhp)
{
    __shared__ __align__(16) float sg[16][68];
    int tid = threadIdx.x;
    int r = tid & 7, g = tid >> 3;          // g < 16
    int b = blockIdx.x * 16 + g;
    float w[8][16];
#pragma unroll
    for (int j = 0; j < 8; ++j)
#pragma unroll
        for (int k = 0; k < 16; ++k) w[j][k] = Whhp[(8 * r + j) * 16 + k];
    float h[16], c[16];
#pragma unroll
    for (int k = 0; k < 16; ++k) { h[k] = 0.f; c[k] = 0.f; }
    float s2  = ((r >> 1) == 2) ? 2.f : 1.f;   // gates 32..47 = g-gate
    float off = s2 - 1.f;

    for (int t = 0; t < 128; ++t) {
        const float* gp = g_Gp + ((size_t)t * B_DIM + b) * 64 + r * 8;
        float4 p0 = *(const float4*)gp;
        float4 p1 = *(const float4*)(gp + 4);
        float gv[8] = {p0.x, p0.y, p0.z, p0.w, p1.x, p1.y, p1.z, p1.w};
        float act[8];
#pragma unroll
        for (int j = 0; j < 8; ++j) {
            float x = gv[j];
#pragma unroll
            for (int k = 0; k < 16; ++k) x += h[k] * w[j][k];
            act[j] = s2 * sigmoidf_(s2 * x) - off;
        }
        __syncwarp();
        *(float4*)&sg[g][r * 8]     = make_float4(act[0], act[1], act[2], act[3]);
        *(float4*)&sg[g][r * 8 + 4] = make_float4(act[4], act[5], act[6], act[7]);
        __syncwarp();
#pragma unroll
        for (int q = 0; q < 4; ++q) {
            float4 iv = *(float4*)&sg[g][      q * 4];
            float4 fv = *(float4*)&sg[g][16 + q * 4];
            float4 gg = *(float4*)&sg[g][32 + q * 4];
            float4 ov = *(float4*)&sg[g][48 + q * 4];
            float ia[4] = {iv.x, iv.y, iv.z, iv.w};
            float fa[4] = {fv.x, fv.y, fv.z, fv.w};
            float ga[4] = {gg.x, gg.y, gg.z, gg.w};
            float oa[4] = {ov.x, ov.y, ov.z, ov.w};
#pragma unroll
            for (int e = 0; e < 4; ++e) {
                int k = q * 4 + e;
                c[k] = fa[e] * c[k] + ia[e] * ga[e];
                h[k] = oa[e] * tanhf_(c[k]);
            }
        }
        if (r == 0) {
            float* out = g_z + ((size_t)t * B_DIM + b) * 16;
            *(float4*)(out)      = make_float4(h[0],  h[1],  h[2],  h[3]);
            *(float4*)(out + 4)  = make_float4(h[4],  h[5],  h[6],  h[7]);
            *(float4*)(out + 8)  = make_float4(h[8],  h[9],  h[10], h[11]);
            *(float4*)(out + 12) = make_float4(h[12], h[13], h[14], h[15]);
        }
    }
}

// =====================================================================
// Kernel 5: softmax denominators. For each (t, c): rs = 1 / sum_b exp(h[t,b].z[t,c])
// (|attn| <= 16, so no max-subtraction needed in fp32)
// =====================================================================
__global__ __launch_bounds__(128) void k_colsum()
{
    __shared__ __align__(16) float hs[512][16];
    int t = blockIdx.y, chunk = blockIdx.x, tid = threadIdx.x;
    const float4* hbase = (const float4*)(g_h + (size_t)t * B_DIM * 16);
    for (int i = tid; i < 2048; i += 128) ((float4*)hs)[i] = hbase[i];
    __syncthreads();
    int c = chunk * 128 + tid;
    const float* zr = g_z + ((size_t)t * B_DIM + c) * 16;
    float4 z0 = *(const float4*)zr,       z1 = *(const float4*)(zr + 4);
    float4 z2 = *(const float4*)(zr + 8), z3 = *(const float4*)(zr + 12);
    float zv[16] = {z0.x, z0.y, z0.z, z0.w, z1.x, z1.y, z1.z, z1.w,
                    z2.x, z2.y, z2.z, z2.w, z3.x, z3.y, z3.z, z3.w};
    float ssum = 0.f;
    for (int b2 = 0; b2 < 512; ++b2) {
        float4 h0 = *(float4*)&hs[b2][0];
        float4 h1 = *(float4*)&hs[b2][4];
        float4 h2 = *(float4*)&hs[b2][8];
        float4 h3 = *(float4*)&hs[b2][12];
        float a = h0.x * zv[0] + h0.y * zv[1] + h0.z * zv[2] + h0.w * zv[3]
                + h1.x * zv[4] + h1.y * zv[5] + h1.z * zv[6] + h1.w * zv[7]
                + h2.x * zv[8] + h2.y * zv[9] + h2.z * zv[10] + h2.w * zv[11]
                + h3.x * zv[12] + h3.y * zv[13] + h3.z * zv[14] + h3.w * zv[15];
        ssum += ex2f(1.4426950408889634f * a);
    }
    g_rs[(size_t)t * B_DIM + c] = 1.0f / ssum;
}

// =====================================================================
// Kernel 6: ctx accumulation + scoring head -> p[t][b]
// =====================================================================
__global__ void k_ctx_out(const float* __restrict__ Wh, const float* __restrict__ We,
                          const float* __restrict__ Wv, float* __restrict__ out)
{
    extern __shared__ __align__(16) float sm[];
    float (*hs)[16] = (float(*)[16])sm;            // 8192 floats
    float (*zs)[16] = (float(*)[16])(sm + 8192);   // 8192 floats
    float* rs = sm + 16384;                        // 512
    float* wh = sm + 16896;                        // 256
    float* we = sm + 17152;                        // 256
    float* wv = sm + 17408;                        // 16
    int t = blockIdx.y, chunk = blockIdx.x, tid = threadIdx.x;
    const float4* hbase = (const float4*)(g_h + (size_t)t * B_DIM * 16);
    const float4* zbase = (const float4*)(g_z + (size_t)t * B_DIM * 16);
    for (int i = tid; i < 2048; i += 128) {
        ((float4*)hs)[i] = hbase[i];
        ((float4*)zs)[i] = zbase[i];
    }
    for (int i = tid; i < 512; i += 128) rs[i] = g_rs[(size_t)t * B_DIM + i];
    for (int i = tid; i < 256; i += 128) { wh[i] = Wh[i]; we[i] = We[i]; }
    if (tid < 16) wv[tid] = Wv[tid];
    __syncthreads();

    int b = chunk * 128 + tid;
    float hb[16];
#pragma unroll
    for (int d = 0; d < 16; ++d) hb[d] = hs[b][d];
    float ctx[16];
#pragma unroll
    for (int d = 0; d < 16; ++d) ctx[d] = 0.f;

    for (int c2 = 0; c2 < 512; ++c2) {
        float4 z0 = *(float4*)&zs[c2][0];
        float4 z1 = *(float4*)&zs[c2][4];
        float4 z2 = *(float4*)&zs[c2][8];
        float4 z3 = *(float4*)&zs[c2][12];
        float a = z0.x * hb[0] + z0.y * hb[1] + z0.z * hb[2] + z0.w * hb[3]
                + z1.x * hb[4] + z1.y * hb[5] + z1.z * hb[6] + z1.w * hb[7]
                + z2.x * hb[8] + z2.y * hb[9] + z2.z * hb[10] + z2.w * hb[11]
                + z3.x * hb[12] + z3.y * hb[13] + z3.z * hb[14] + z3.w * hb[15];
        float wgt = ex2f(1.4426950408889634f * a) * rs[c2];
        float4 h0 = *(float4*)&hs[c2][0];
        float4 h1 = *(float4*)&hs[c2][4];
        float4 h2 = *(float4*)&hs[c2][8];
        float4 h3 = *(float4*)&hs[c2][12];
        ctx[0]  += wgt * h0.x; ctx[1]  += wgt * h0.y; ctx[2]  += wgt * h0.z; ctx[3]  += wgt * h0.w;
        ctx[4]  += wgt * h1.x; ctx[5]  += wgt * h1.y; ctx[6]  += wgt * h1.z; ctx[7]  += wgt * h1.w;
        ctx[8]  += wgt * h2.x; ctx[9]  += wgt * h2.y; ctx[10] += wgt * h2.z; ctx[11] += wgt * h2.w;
        ctx[12] += wgt * h3.x; ctx[13] += wgt * h3.y; ctx[14] += wgt * h3.z; ctx[15] += wgt * h3.w;
    }
    float p = 0.f;
#pragma unroll
    for (int e = 0; e < 16; ++e) {
        float u = 0.f;
#pragma unroll
        for (int d = 0; d < 16; ++d) u += hb[d] * wh[e * 16 + d] + ctx[d] * we[e * 16 + d];
        p += tanhf_(u) * wv[e];
    }
    out[(size_t)t * B_DIM + b] = sigmoidf_(p);
}

// =====================================================================
extern "C" void kernel_launch(void* const* d_in, const int* in_sizes, int n_in,
                              void* d_out, int out_size)
{
    (void)in_sizes; (void)n_in; (void)out_size;
    const float* X     = (const float*)d_in[0];
    const float* Wih_f = (const float*)d_in[1];
    const float* Whh_f = (const float*)d_in[2];
    const float* bih_f = (const float*)d_in[3];
    const float* bhh_f = (const float*)d_in[4];
    const float* Wih_b = (const float*)d_in[5];
    const float* Whh_b = (const float*)d_in[6];
    const float* bih_b = (const float*)d_in[7];
    const float* bhh_b = (const float*)d_in[8];
    const float* Wih_p = (const float*)d_in[9];
    const float* Whh_p = (const float*)d_in[10];
    const float* bih_p = (const float*)d_in[11];
    const float* bhh_p = (const float*)d_in[12];
    const float* W_h   = (const float*)d_in[13];
    const float* W_e   = (const float*)d_in[14];
    const float* W_v   = (const float*)d_in[15];
    float* out = (float*)d_out;

    k_gemm_in<<<512, 256>>>(X, Wih_f, Wih_b, bih_f, bhh_f, bih_b, bhh_b);
    k_bilstm<<<dim3(16, 2), 128>>>(Whh_f, Whh_b);
    k_gp<<<TB / 4, 256>>>(Wih_p, bih_p, bhh_p);
    k_ptr<<<32, 128>>>(Whh_p);
    k_colsum<<<dim3(4, T_DIM), 128>>>();
    cudaFuncSetAttribute(k_ctx_out, cudaFuncAttributeMaxDynamicSharedMemorySize, 69696);
    k_ctx_out<<<dim3(4, T_DIM), 128, 69696>>>(W_h, W_e, W_v, out);
}

// round 5
// speedup vs baseline: 1.1776x; 1.1776x over previous
#include <cuda_runtime.h>

typedef unsigned long long ull;

#define T_DIM 128
#define B_DIM 512
#define D_IN  768
#define TB    (T_DIM * B_DIM)   // 65536
#define LOG2E 1.4426950408889634f

// ---------------- scratch (device globals; no allocations) ----------------
__device__ float g_G [TB * 64];   // bi-LSTM input-proj gates (fwd 0..31, bwd 32..63)
__device__ float g_h [TB * 16];   // concat bi-LSTM hidden  [t][b][16]
__device__ float g_Gp[TB * 64];   // ptr-LSTM input-proj gates
__device__ float g_z [TB * 16];   // ptr-LSTM hidden
__device__ float g_rs[TB];        // 1 / column-softmax-denominator, [t][c]

// ---------------- fast activations ----------------
__device__ __forceinline__ float ex2f(float x) { float y; asm("ex2.approx.ftz.f32 %0, %1;" : "=f"(y) : "f"(x)); return y; }
__device__ __forceinline__ float rcpf(float x) { float y; asm("rcp.approx.ftz.f32 %0, %1;" : "=f"(y) : "f"(x)); return y; }
__device__ __forceinline__ float sigmoidf_(float x) { return rcpf(1.f + ex2f(-LOG2E * x)); }
__device__ __forceinline__ float tanhf_(float x)    { return 2.f * sigmoidf_(2.f * x) - 1.f; }

// ---------------- packed f32x2 helpers (sm_100+) ----------------
__device__ __forceinline__ ull ffma2(ull a, ull b, ull c) {
    ull d; asm("fma.rn.f32x2 %0, %1, %2, %3;" : "=l"(d) : "l"(a), "l"(b), "l"(c)); return d;
}
__device__ __forceinline__ ull fmul2(ull a, ull b) {
    ull d; asm("mul.rn.f32x2 %0, %1, %2;" : "=l"(d) : "l"(a), "l"(b)); return d;
}
__device__ __forceinline__ ull pack2(float x, float y) {
    ull d; asm("mov.b64 %0, {%1, %2};" : "=l"(d) : "f"(x), "f"(y)); return d;
}
__device__ __forceinline__ void unpk2(ull d, float& x, float& y) {
    asm("mov.b64 {%0, %1}, %2;" : "=f"(x), "=f"(y) : "l"(d));
}
__device__ __forceinline__ float hsum2(ull d) { float x, y; unpk2(d, x, y); return x + y; }

// =====================================================================
// Kernel 1: input GEMM  G[m][n] = X[m][:] . W2[n][:] + bias[n]
//   M=65536, N=64 (0..31 = Wih_f rows, 32..63 = Wih_b rows), K=768
//   f32x2 packed FMA; A stored k-major transposed (conflict-free LDS.128);
//   B stored as pre-duplicated (b,b) pairs.
// =====================================================================
__global__ __launch_bounds__(128) void k_gemm_in(
    const float* __restrict__ X,
    const float* __restrict__ Wf, const float* __restrict__ Wb,
    const float* __restrict__ bihf, const float* __restrict__ bhhf,
    const float* __restrict__ bihb, const float* __restrict__ bhhb)
{
    __shared__ __align__(16) float At[32][132];   // [k][m], pad -> conflict-free
    __shared__ __align__(16) ull   Bs2[32][66];   // [k][n] as (b,b) pairs
    int tid = threadIdx.x;
    int m0  = blockIdx.x * 128;
    int tx  = tid & 15, ty = tid >> 4;   // tx: n-group of 4, ty: m-group of 16
    ull acc[8][4];
#pragma unroll
    for (int p = 0; p < 8; ++p)
#pragma unroll
        for (int n = 0; n < 4; ++n) acc[p][n] = 0ull;

    for (int k0 = 0; k0 < D_IN; k0 += 32) {
#pragma unroll
        for (int i = 0; i < 8; ++i) {            // A tile: 1024 float4, transpose into At
            int idx = tid + i * 128;
            int m = idx >> 3, kk = (idx & 7) << 2;
            float4 v = *(const float4*)(X + (size_t)(m0 + m) * D_IN + k0 + kk);
            At[kk + 0][m] = v.x; At[kk + 1][m] = v.y; At[kk + 2][m] = v.z; At[kk + 3][m] = v.w;
        }
#pragma unroll
        for (int i = 0; i < 4; ++i) {            // B tile: 512 float4 -> duplicated pairs
            int idx = tid + i * 128;
            int n = idx >> 3, kk = (idx & 7) << 2;
            const float* src = (n < 32) ? (Wf + (size_t)n * D_IN) : (Wb + (size_t)(n - 32) * D_IN);
            float4 v = *(const float4*)(src + k0 + kk);
            Bs2[kk + 0][n] = pack2(v.x, v.x); Bs2[kk + 1][n] = pack2(v.y, v.y);
            Bs2[kk + 2][n] = pack2(v.z, v.z); Bs2[kk + 3][n] = pack2(v.w, v.w);
        }
        __syncthreads();
#pragma unroll
        for (int k = 0; k < 32; ++k) {
            const ulonglong2* ap = (const ulonglong2*)&At[k][ty * 16];
            ulonglong2 a01 = ap[0], a23 = ap[1], a45 = ap[2], a67 = ap[3];
            ull a[8] = {a01.x, a01.y, a23.x, a23.y, a45.x, a45.y, a67.x, a67.y};
            const ulonglong2* bp = (const ulonglong2*)&Bs2[k][tx * 4];
            ulonglong2 b01 = bp[0], b23 = bp[1];
            ull bb[4] = {b01.x, b01.y, b23.x, b23.y};
#pragma unroll
            for (int p = 0; p < 8; ++p)
#pragma unroll
                for (int n = 0; n < 4; ++n) acc[p][n] = ffma2(a[p], bb[n], acc[p][n]);
        }
        __syncthreads();
    }
    float bias[4];
#pragma unroll
    for (int n = 0; n < 4; ++n) {
        int nn = tx * 4 + n;
        bias[n] = (nn < 32) ? (bihf[nn] + bhhf[nn]) : (bihb[nn - 32] + bhhb[nn - 32]);
    }
#pragma unroll
    for (int p = 0; p < 8; ++p) {
        float lo[4], hi[4];
#pragma unroll
        for (int n = 0; n < 4; ++n) unpk2(acc[p][n], lo[n], hi[n]);
        int m = m0 + ty * 16 + 2 * p;
        *(float4*)(g_G + (size_t)m * 64 + tx * 4) =
            make_float4(lo[0] + bias[0], lo[1] + bias[1], lo[2] + bias[2], lo[3] + bias[3]);
        *(float4*)(g_G + (size_t)(m + 1) * 64 + tx * 4) =
            make_float4(hi[0] + bias[0], hi[1] + bias[1], hi[2] + bias[2], hi[3] + bias[3]);
    }
}

// =====================================================================
// Kernel 2: bi-LSTM scan. 8 lanes per (item, direction); lane l owns
// hidden unit l: computes gate rows {l, 8+l, 16+l, 24+l}, one tanh(c).
// h exchanged via shfl. Distance-2 gate prefetch hides L2 latency.
// =====================================================================
__global__ __launch_bounds__(128) void k_bilstm(const float* __restrict__ WhhF,
                                                const float* __restrict__ WhhB)
{
    int dir = blockIdx.y;
    int tid = threadIdx.x;
    int l = tid & 7, g = tid >> 3;          // g < 16
    int b = blockIdx.x * 16 + g;
    const float* Whh = dir ? WhhB : WhhF;
    ull w2[4][4];
#pragma unroll
    for (int q = 0; q < 4; ++q) {
        const float* wr = Whh + (size_t)(8 * q + l) * 8;
#pragma unroll
        for (int j = 0; j < 4; ++j) w2[q][j] = pack2(wr[2 * j], wr[2 * j + 1]);
    }
    ull h2[4] = {0ull, 0ull, 0ull, 0ull};
    float c = 0.f;
    unsigned base = (tid & 31) & ~7u;
    const float* gbase = g_G + (size_t)b * 64 + dir * 32 + l;
    const int TS = B_DIM * 64;
    float* hout = g_h + (size_t)b * 16 + dir * 8 + l;

    float buf0[4], buf1[4];
    {
        const float* p = gbase + (size_t)(dir ? 127 : 0) * TS;
        buf0[0] = p[0]; buf0[1] = p[8]; buf0[2] = p[16]; buf0[3] = p[24];
        p = gbase + (size_t)(dir ? 126 : 1) * TS;
        buf1[0] = p[0]; buf1[1] = p[8]; buf1[2] = p[16]; buf1[3] = p[24];
    }

    auto step = [&](float* bf, int s) {
        float xs[4] = {bf[0], bf[1], bf[2], bf[3]};
        if (s < 126) {                                    // prefetch s+2
            int tn = dir ? (125 - s) : (s + 2);
            const float* p = gbase + (size_t)tn * TS;
            bf[0] = p[0]; bf[1] = p[8]; bf[2] = p[16]; bf[3] = p[24];
        }
#pragma unroll
        for (int q = 0; q < 4; ++q) {
            ull d = fmul2(h2[0], w2[q][0]);
            d = ffma2(h2[1], w2[q][1], d);
            d = ffma2(h2[2], w2[q][2], d);
            d = ffma2(h2[3], w2[q][3], d);
            xs[q] += hsum2(d);
        }
        float iv = sigmoidf_(xs[0]), fv = sigmoidf_(xs[1]);
        float gv = tanhf_(xs[2]),    ov = sigmoidf_(xs[3]);
        c = fv * c + iv * gv;
        float hn = ov * tanhf_(c);
        int t = dir ? (127 - s) : s;
        hout[(size_t)t * (B_DIM * 16)] = hn;
        float h0 = __shfl_sync(0xffffffffu, hn, base + 0);
        float h1 = __shfl_sync(0xffffffffu, hn, base + 1);
        float h3_ = __shfl_sync(0xffffffffu, hn, base + 3);
        float h2_ = __shfl_sync(0xffffffffu, hn, base + 2);
        float h4 = __shfl_sync(0xffffffffu, hn, base + 4);
        float h5 = __shfl_sync(0xffffffffu, hn, base + 5);
        float h6 = __shfl_sync(0xffffffffu, hn, base + 6);
        float h7 = __shfl_sync(0xffffffffu, hn, base + 7);
        h2[0] = pack2(h0, h1); h2[1] = pack2(h2_, h3_);
        h2[2] = pack2(h4, h5); h2[3] = pack2(h6, h7);
    };
    for (int s = 0; s < 128; s += 2) { step(buf0, s); step(buf1, s + 1); }
}

// =====================================================================
// Kernel 3: ptr-LSTM input projection  Gp[m][n] = h[m][:] . Wih_p[n][:] + bias
// =====================================================================
__global__ __launch_bounds__(256) void k_gp(const float* __restrict__ Wihp,
                                            const float* __restrict__ bihp,
                                            const float* __restrict__ bhhp)
{
    __shared__ float Wp[64][17];
    __shared__ float bs[64];
    int tid = threadIdx.x;
    if (tid < 64) bs[tid] = bihp[tid] + bhhp[tid];
    for (int i = tid; i < 1024; i += 256) Wp[i >> 4][i & 15] = Wihp[i];
    __syncthreads();
    int n  = tid & 63, mi = tid >> 6;
    int m  = blockIdx.x * 4 + mi;
    const float* hr = g_h + (size_t)m * 16;
    float4 h0 = *(const float4*)hr,       h1 = *(const float4*)(hr + 4);
    float4 h2 = *(const float4*)(hr + 8), h3 = *(const float4*)(hr + 12);
    float hv[16] = {h0.x, h0.y, h0.z, h0.w, h1.x, h1.y, h1.z, h1.w,
                    h2.x, h2.y, h2.z, h2.w, h3.x, h3.y, h3.z, h3.w};
    float acc = bs[n];
#pragma unroll
    for (int k = 0; k < 16; ++k) acc += hv[k] * Wp[n][k];
    g_Gp[(size_t)m * 64 + n] = acc;
}

// =====================================================================
// Kernel 4: ptr-LSTM scan. 16 lanes/item; lane l owns hidden unit l:
// gate rows {l, 16+l, 32+l, 48+l}; shfl h-exchange; distance-2 prefetch.
// =====================================================================
__global__ __launch_bounds__(128) void k_ptr(const float* __restrict__ Whhp)
{
    int tid = threadIdx.x;
    int l = tid & 15, g = tid >> 4;         // g < 8
    int b = blockIdx.x * 8 + g;
    ull w2[4][8];
#pragma unroll
    for (int q = 0; q < 4; ++q) {
        const float* wr = Whhp + (size_t)(16 * q + l) * 16;
#pragma unroll
        for (int j = 0; j < 8; ++j) w2[q][j] = pack2(wr[2 * j], wr[2 * j + 1]);
    }
    ull h2[8];
#pragma unroll
    for (int j = 0; j < 8; ++j) h2[j] = 0ull;
    float c = 0.f;
    unsigned base = (tid & 31) & ~15u;
    const float* gbase = g_Gp + (size_t)b * 64 + l;
    const int TS = B_DIM * 64;
    float* zout = g_z + (size_t)b * 16 + l;

    float buf0[4], buf1[4];
    {
        const float* p = gbase;
        buf0[0] = p[0]; buf0[1] = p[16]; buf0[2] = p[32]; buf0[3] = p[48];
        p = gbase + TS;
        buf1[0] = p[0]; buf1[1] = p[16]; buf1[2] = p[32]; buf1[3] = p[48];
    }

    auto step = [&](float* bf, int t) {
        float xs[4] = {bf[0], bf[1], bf[2], bf[3]};
        if (t < 126) {                                  // prefetch t+2
            const float* p = gbase + (size_t)(t + 2) * TS;
            bf[0] = p[0]; bf[1] = p[16]; bf[2] = p[32]; bf[3] = p[48];
        }
#pragma unroll
        for (int q = 0; q < 4; ++q) {
            ull d = fmul2(h2[0], w2[q][0]);
#pragma unroll
            for (int j = 1; j < 8; ++j) d = ffma2(h2[j], w2[q][j], d);
            xs[q] += hsum2(d);
        }
        float iv = sigmoidf_(xs[0]), fv = sigmoidf_(xs[1]);
        float gv = tanhf_(xs[2]),    ov = sigmoidf_(xs[3]);
        c = fv * c + iv * gv;
        float hn = ov * tanhf_(c);
        zout[(size_t)t * (B_DIM * 16)] = hn;
        float hv[16];
#pragma unroll
        for (int j = 0; j < 16; ++j) hv[j] = __shfl_sync(0xffffffffu, hn, base + j);
#pragma unroll
        for (int j = 0; j < 8; ++j) h2[j] = pack2(hv[2 * j], hv[2 * j + 1]);
    };
    for (int t = 0; t < 128; t += 2) { step(buf0, t); step(buf1, t + 1); }
}

// =====================================================================
// Kernel 5: softmax denominators. rs[t][c] = 1 / sum_b exp(h[t,b].z[t,c])
// (|attn| <= 16 -> no max subtraction needed in fp32)
// =====================================================================
__global__ __launch_bounds__(128) void k_colsum()
{
    __shared__ __align__(16) float hs[512][16];
    int t = blockIdx.y, chunk = blockIdx.x, tid = threadIdx.x;
    const float4* hbase = (const float4*)(g_h + (size_t)t * B_DIM * 16);
    for (int i = tid; i < 2048; i += 128) ((float4*)hs)[i] = hbase[i];
    __syncthreads();
    int cidx = chunk * 128 + tid;
    const ull* zp = (const ull*)(g_z + ((size_t)t * B_DIM + cidx) * 16);
    ull z2[8];
#pragma unroll
    for (int j = 0; j < 8; ++j) z2[j] = zp[j];
    float ssum = 0.f;
    for (int b2 = 0; b2 < 512; ++b2) {
        const ulonglong2* hp = (const ulonglong2*)hs[b2];
        ulonglong2 q0 = hp[0], q1 = hp[1], q2 = hp[2], q3 = hp[3];
        ull d = fmul2(q0.x, z2[0]);
        d = ffma2(q0.y, z2[1], d); d = ffma2(q1.x, z2[2], d); d = ffma2(q1.y, z2[3], d);
        d = ffma2(q2.x, z2[4], d); d = ffma2(q2.y, z2[5], d);
        d = ffma2(q3.x, z2[6], d); d = ffma2(q3.y, z2[7], d);
        ssum += ex2f(LOG2E * hsum2(d));
    }
    g_rs[(size_t)t * B_DIM + cidx] = 1.0f / ssum;
}

// =====================================================================
// Kernel 6: ctx accumulation + scoring head -> p[t][b]   (f32x2)
// =====================================================================
__global__ void k_ctx_out(const float* __restrict__ Wh, const float* __restrict__ We,
                          const float* __restrict__ Wv, float* __restrict__ out)
{
    extern __shared__ __align__(16) float sm[];
    float (*hs)[16] = (float(*)[16])sm;            // 8192 floats
    float (*zs)[16] = (float(*)[16])(sm + 8192);   // 8192 floats
    float* rs = sm + 16384;                        // 512
    float* wh = sm + 16896;                        // 256
    float* we = sm + 17152;                        // 256
    float* wv = sm + 17408;                        // 16
    int t = blockIdx.y, chunk = blockIdx.x, tid = threadIdx.x;
    const float4* hbase = (const float4*)(g_h + (size_t)t * B_DIM * 16);
    const float4* zbase = (const float4*)(g_z + (size_t)t * B_DIM * 16);
    for (int i = tid; i < 2048; i += 128) {
        ((float4*)hs)[i] = hbase[i];
        ((float4*)zs)[i] = zbase[i];
    }
    for (int i = tid; i < 512; i += 128) rs[i] = g_rs[(size_t)t * B_DIM + i];
    for (int i = tid; i < 256; i += 128) { wh[i] = Wh[i]; we[i] = We[i]; }
    if (tid < 16) wv[tid] = Wv[tid];
    __syncthreads();

    int b = chunk * 128 + tid;
    float hb[16];
#pragma unroll
    for (int d = 0; d < 16; ++d) hb[d] = hs[b][d];
    ull hb2[8];
#pragma unroll
    for (int j = 0; j < 8; ++j) hb2[j] = pack2(hb[2 * j], hb[2 * j + 1]);
    ull ctx2[8];
#pragma unroll
    for (int j = 0; j < 8; ++j) ctx2[j] = 0ull;

    for (int c2 = 0; c2 < 512; ++c2) {
        const ulonglong2* zp = (const ulonglong2*)zs[c2];
        ulonglong2 q0 = zp[0], q1 = zp[1], q2 = zp[2], q3 = zp[3];
        ull d = fmul2(q0.x, hb2[0]);
        d = ffma2(q0.y, hb2[1], d); d = ffma2(q1.x, hb2[2], d); d = ffma2(q1.y, hb2[3], d);
        d = ffma2(q2.x, hb2[4], d); d = ffma2(q2.y, hb2[5], d);
        d = ffma2(q3.x, hb2[6], d); d = ffma2(q3.y, hb2[7], d);
        float wgt = ex2f(LOG2E * hsum2(d)) * rs[c2];
        ull wp = pack2(wgt, wgt);
        const ulonglong2* hp = (const ulonglong2*)hs[c2];
        ulonglong2 p0 = hp[0], p1 = hp[1], p2 = hp[2], p3 = hp[3];
        ctx2[0] = ffma2(wp, p0.x, ctx2[0]); ctx2[1] = ffma2(wp, p0.y, ctx2[1]);
        ctx2[2] = ffma2(wp, p1.x, ctx2[2]); ctx2[3] = ffma2(wp, p1.y, ctx2[3]);
        ctx2[4] = ffma2(wp, p2.x, ctx2[4]); ctx2[5] = ffma2(wp, p2.y, ctx2[5]);
        ctx2[6] = ffma2(wp, p3.x, ctx2[6]); ctx2[7] = ffma2(wp, p3.y, ctx2[7]);
    }
    float ctx[16];
#pragma unroll
    for (int j = 0; j < 8; ++j) unpk2(ctx2[j], ctx[2 * j], ctx[2 * j + 1]);

    float p = 0.f;
#pragma unroll
    for (int e = 0; e < 16; ++e) {
        float u = 0.f;
#pragma unroll
        for (int d = 0; d < 16; ++d) u += hb[d] * wh[e * 16 + d] + ctx[d] * we[e * 16 + d];
        p += tanhf_(u) * wv[e];
    }
    out[(size_t)t * B_DIM + b] = sigmoidf_(p);
}

// =====================================================================
extern "C" void kernel_launch(void* const* d_in, const int* in_sizes, int n_in,
                              void* d_out, int out_size)
{
    (void)in_sizes; (void)n_in; (void)out_size;
    const float* X     = (const float*)d_in[0];
    const float* Wih_f = (const float*)d_in[1];
    const float* Whh_f = (const float*)d_in[2];
    const float* bih_f = (const float*)d_in[3];
    const float* bhh_f = (const float*)d_in[4];
    const float* Wih_b = (const float*)d_in[5];
    const float* Whh_b = (const float*)d_in[6];
    const float* bih_b = (const float*)d_in[7];
    const float* bhh_b = (const float*)d_in[8];
    const float* Wih_p = (const float*)d_in[9];
    const float* Whh_p = (const float*)d_in[10];
    const float* bih_p = (const float*)d_in[11];
    const float* bhh_p = (const float*)d_in[12];
    const float* W_h   = (const float*)d_in[13];
    const float* W_e   = (const float*)d_in[14];
    const float* W_v   = (const float*)d_in[15];
    float* out = (float*)d_out;

    k_gemm_in<<<512, 128>>>(X, Wih_f, Wih_b, bih_f, bhh_f, bih_b, bhh_b);
    k_bilstm<<<dim3(32, 2), 128>>>(Whh_f, Whh_b);
    k_gp<<<TB / 4, 256>>>(Wih_p, bih_p, bhh_p);
    k_ptr<<<64, 128>>>(Whh_p);
    k_colsum<<<dim3(4, T_DIM), 128>>>();
    cudaFuncSetAttribute(k_ctx_out, cudaFuncAttributeMaxDynamicSharedMemorySize, 69696);
    k_ctx_out<<<dim3(4, T_DIM), 128, 69696>>>(W_h, W_e, W_v, out);
}

// round 8
// speedup vs baseline: 1.3059x; 1.1089x over previous
#include <cuda_runtime.h>

typedef unsigned long long ull;

#define T_DIM 128
#define B_DIM 512
#define D_IN  768
#define TB    (T_DIM * B_DIM)   // 65536
#define LOG2E 1.4426950408889634f

// ---------------- scratch (device globals; no allocations) ----------------
__device__ float g_G [TB * 64];   // bi-LSTM input-proj gates (fwd 0..31, bwd 32..63)
__device__ float g_h [TB * 16];   // concat bi-LSTM hidden  [t][b][16]
__device__ float g_Gp[TB * 64];   // ptr-LSTM input-proj gates
__device__ float g_z [TB * 16];   // ptr-LSTM hidden
__device__ float g_rs[TB];        // 1 / column-softmax-denominator, [t][c]

// ---------------- fast activations ----------------
__device__ __forceinline__ float ex2f(float x) { float y; asm("ex2.approx.ftz.f32 %0, %1;" : "=f"(y) : "f"(x)); return y; }
__device__ __forceinline__ float rcpf(float x) { float y; asm("rcp.approx.ftz.f32 %0, %1;" : "=f"(y) : "f"(x)); return y; }
__device__ __forceinline__ float sigmoidf_(float x) { return rcpf(1.f + ex2f(-LOG2E * x)); }
__device__ __forceinline__ float tanhf_(float x)    { return 2.f * sigmoidf_(2.f * x) - 1.f; }

// ---------------- packed f32x2 helpers (sm_100+) ----------------
__device__ __forceinline__ ull ffma2(ull a, ull b, ull c) {
    ull d; asm("fma.rn.f32x2 %0, %1, %2, %3;" : "=l"(d) : "l"(a), "l"(b), "l"(c)); return d;
}
__device__ __forceinline__ ull fmul2(ull a, ull b) {
    ull d; asm("mul.rn.f32x2 %0, %1, %2;" : "=l"(d) : "l"(a), "l"(b)); return d;
}
__device__ __forceinline__ ull pack2(float x, float y) {
    ull d; asm("mov.b64 %0, {%1, %2};" : "=l"(d) : "f"(x), "f"(y)); return d;
}
__device__ __forceinline__ void unpk2(ull d, float& x, float& y) {
    asm("mov.b64 {%0, %1}, %2;" : "=f"(x), "=f"(y) : "l"(d));
}
__device__ __forceinline__ float hsum2(ull d) { float x, y; unpk2(d, x, y); return x + y; }

// =====================================================================
// Kernel 1: input GEMM  G[m][n] = X[m][:] . W2[n][:] + bias[n]
//   M=65536, N=64 (0..31 = Wih_f rows, 32..63 = Wih_b rows), K=768
// =====================================================================
__global__ __launch_bounds__(128) void k_gemm_in(
    const float* __restrict__ X,
    const float* __restrict__ Wf, const float* __restrict__ Wb,
    const float* __restrict__ bihf, const float* __restrict__ bhhf,
    const float* __restrict__ bihb, const float* __restrict__ bhhb)
{
    __shared__ __align__(16) float At[32][132];   // [k][m], pad -> conflict-free
    __shared__ __align__(16) ull   Bs2[32][66];   // [k][n] as (b,b) pairs
    int tid = threadIdx.x;
    int m0  = blockIdx.x * 128;
    int tx  = tid & 15, ty = tid >> 4;   // tx: n-group of 4, ty: m-group of 16
    ull acc[8][4];
#pragma unroll
    for (int p = 0; p < 8; ++p)
#pragma unroll
        for (int n = 0; n < 4; ++n) acc[p][n] = 0ull;

    for (int k0 = 0; k0 < D_IN; k0 += 32) {
#pragma unroll
        for (int i = 0; i < 8; ++i) {            // A tile: 1024 float4, transpose into At
            int idx = tid + i * 128;
            int m = idx >> 3, kk = (idx & 7) << 2;
            float4 v = *(const float4*)(X + (size_t)(m0 + m) * D_IN + k0 + kk);
            At[kk + 0][m] = v.x; At[kk + 1][m] = v.y; At[kk + 2][m] = v.z; At[kk + 3][m] = v.w;
        }
#pragma unroll
        for (int i = 0; i < 4; ++i) {            // B tile: 512 float4 -> duplicated pairs
            int idx = tid + i * 128;
            int n = idx >> 3, kk = (idx & 7) << 2;
            const float* src = (n < 32) ? (Wf + (size_t)n * D_IN) : (Wb + (size_t)(n - 32) * D_IN);
            float4 v = *(const float4*)(src + k0 + kk);
            Bs2[kk + 0][n] = pack2(v.x, v.x); Bs2[kk + 1][n] = pack2(v.y, v.y);
            Bs2[kk + 2][n] = pack2(v.z, v.z); Bs2[kk + 3][n] = pack2(v.w, v.w);
        }
        __syncthreads();
#pragma unroll
        for (int k = 0; k < 32; ++k) {
            const ulonglong2* ap = (const ulonglong2*)&At[k][ty * 16];
            ulonglong2 a01 = ap[0], a23 = ap[1], a45 = ap[2], a67 = ap[3];
            ull a[8] = {a01.x, a01.y, a23.x, a23.y, a45.x, a45.y, a67.x, a67.y};
            const ulonglong2* bp = (const ulonglong2*)&Bs2[k][tx * 4];
            ulonglong2 b01 = bp[0], b23 = bp[1];
            ull bb[4] = {b01.x, b01.y, b23.x, b23.y};
#pragma unroll
            for (int p = 0; p < 8; ++p)
#pragma unroll
                for (int n = 0; n < 4; ++n) acc[p][n] = ffma2(a[p], bb[n], acc[p][n]);
        }
        __syncthreads();
    }
    float bias[4];
#pragma unroll
    for (int n = 0; n < 4; ++n) {
        int nn = tx * 4 + n;
        bias[n] = (nn < 32) ? (bihf[nn] + bhhf[nn]) : (bihb[nn - 32] + bhhb[nn - 32]);
    }
#pragma unroll
    for (int p = 0; p < 8; ++p) {
        float lo[4], hi[4];
#pragma unroll
        for (int n = 0; n < 4; ++n) unpk2(acc[p][n], lo[n], hi[n]);
        int m = m0 + ty * 16 + 2 * p;
        *(float4*)(g_G + (size_t)m * 64 + tx * 4) =
            make_float4(lo[0] + bias[0], lo[1] + bias[1], lo[2] + bias[2], lo[3] + bias[3]);
        *(float4*)(g_G + (size_t)(m + 1) * 64 + tx * 4) =
            make_float4(hi[0] + bias[0], hi[1] + bias[1], hi[2] + bias[2], hi[3] + bias[3]);
    }
}

// =====================================================================
// Kernel 2: bi-LSTM scan, 2 independent (item,dir) pairs PER THREAD.
// Warp = 4 groups of 8 lanes; lane l owns hidden unit l of both pairs.
// 128 one-warp blocks -> 128 SMs busy; dual chains hide each other's
// MUFU/shfl latency.
// =====================================================================
__global__ __launch_bounds__(32) void k_bilstm(const float* __restrict__ WhhF,
                                               const float* __restrict__ WhhB)
{
    int lane = threadIdx.x;
    int l = lane & 7, g2 = lane >> 3;            // g2 < 4
    int p0 = blockIdx.x * 8 + g2 * 2;            // pair indices p0, p0+1 (same dir)
    int dir = p0 >> 9;
    int b0 = p0 & 511;
    const float* Whh = dir ? WhhB : WhhF;
    ull w2[4][4];
#pragma unroll
    for (int q = 0; q < 4; ++q) {
        const float* wr = Whh + (size_t)(8 * q + l) * 8;
#pragma unroll
        for (int j = 0; j < 4; ++j) w2[q][j] = pack2(wr[2 * j], wr[2 * j + 1]);
    }
    ull h2[2][4];
    float c[2] = {0.f, 0.f};
#pragma unroll
    for (int it = 0; it < 2; ++it)
#pragma unroll
        for (int j = 0; j < 4; ++j) h2[it][j] = 0ull;
    unsigned base = lane & ~7u;
    const int TS = B_DIM * 64;
    const float* gb[2];
    float* ho[2];
#pragma unroll
    for (int it = 0; it < 2; ++it) {
        gb[it] = g_G + (size_t)(b0 + it) * 64 + dir * 32 + l;
        ho[it] = g_h + (size_t)(b0 + it) * 16 + dir * 8 + l;
    }

    float buf0[2][4], buf1[2][4];
#pragma unroll
    for (int it = 0; it < 2; ++it) {
        const float* p = gb[it] + (size_t)(dir ? 127 : 0) * TS;
        buf0[it][0] = p[0]; buf0[it][1] = p[8]; buf0[it][2] = p[16]; buf0[it][3] = p[24];
        p = gb[it] + (size_t)(dir ? 126 : 1) * TS;
        buf1[it][0] = p[0]; buf1[it][1] = p[8]; buf1[it][2] = p[16]; buf1[it][3] = p[24];
    }

    auto step = [&](float (&bf)[2][4], int s) {
        float xs[2][4];
#pragma unroll
        for (int it = 0; it < 2; ++it)
#pragma unroll
            for (int q = 0; q < 4; ++q) xs[it][q] = bf[it][q];
        if (s < 126) {                                    // prefetch s+2 for both items
            int tn = dir ? (125 - s) : (s + 2);
#pragma unroll
            for (int it = 0; it < 2; ++it) {
                const float* p = gb[it] + (size_t)tn * TS;
                bf[it][0] = p[0]; bf[it][1] = p[8]; bf[it][2] = p[16]; bf[it][3] = p[24];
            }
        }
#pragma unroll
        for (int it = 0; it < 2; ++it)
#pragma unroll
            for (int q = 0; q < 4; ++q) {
                ull d = fmul2(h2[it][0], w2[q][0]);
                d = ffma2(h2[it][1], w2[q][1], d);
                d = ffma2(h2[it][2], w2[q][2], d);
                d = ffma2(h2[it][3], w2[q][3], d);
                xs[it][q] += hsum2(d);
            }
        int t = dir ? (127 - s) : s;
        float hn[2];
#pragma unroll
        for (int it = 0; it < 2; ++it) {
            float iv = sigmoidf_(xs[it][0]), fv = sigmoidf_(xs[it][1]);
            float gv = tanhf_(xs[it][2]),    ov = sigmoidf_(xs[it][3]);
            c[it] = fv * c[it] + iv * gv;
            hn[it] = ov * tanhf_(c[it]);
            ho[it][(size_t)t * (B_DIM * 16)] = hn[it];
        }
#pragma unroll
        for (int j = 0; j < 4; ++j) {
            float a0 = __shfl_sync(0xffffffffu, hn[0], base + 2 * j);
            float a1 = __shfl_sync(0xffffffffu, hn[0], base + 2 * j + 1);
            float b0v = __shfl_sync(0xffffffffu, hn[1], base + 2 * j);
            float b1v = __shfl_sync(0xffffffffu, hn[1], base + 2 * j + 1);
            h2[0][j] = pack2(a0, a1);
            h2[1][j] = pack2(b0v, b1v);
        }
    };
    for (int s = 0; s < 128; s += 2) { step(buf0, s); step(buf1, s + 1); }
}

// =====================================================================
// Kernel 3: ptr-LSTM input projection  Gp[m][n] = h[m][:] . Wih_p[n][:] + bias
// =====================================================================
__global__ __launch_bounds__(256) void k_gp(const float* __restrict__ Wihp,
                                            const float* __restrict__ bihp,
                                            const float* __restrict__ bhhp)
{
    __shared__ float Wp[64][17];
    __shared__ float bs[64];
    int tid = threadIdx.x;
    if (tid < 64) bs[tid] = bihp[tid] + bhhp[tid];
    for (int i = tid; i < 1024; i += 256) Wp[i >> 4][i & 15] = Wihp[i];
    __syncthreads();
    int n  = tid & 63, mi = tid >> 6;
    int m  = blockIdx.x * 4 + mi;
    const float* hr = g_h + (size_t)m * 16;
    float4 h0 = *(const float4*)hr,       h1 = *(const float4*)(hr + 4);
    float4 h2 = *(const float4*)(hr + 8), h3 = *(const float4*)(hr + 12);
    float hv[16] = {h0.x, h0.y, h0.z, h0.w, h1.x, h1.y, h1.z, h1.w,
                    h2.x, h2.y, h2.z, h2.w, h3.x, h3.y, h3.z, h3.w};
    float acc = bs[n];
#pragma unroll
    for (int k = 0; k < 16; ++k) acc += hv[k] * Wp[n][k];
    g_Gp[(size_t)m * 64 + n] = acc;
}

// =====================================================================
// Kernel 4: ptr-LSTM scan, 2 items PER THREAD. Warp = 2 groups of 16
// lanes; lane l owns hidden unit l of both items. 128 one-warp blocks.
// =====================================================================
__global__ __launch_bounds__(32) void k_ptr(const float* __restrict__ Whhp)
{
    int lane = threadIdx.x;
    int l = lane & 15, g2 = lane >> 4;           // g2 < 2
    int b0 = blockIdx.x * 4 + g2 * 2;            // items b0, b0+1
    ull w2[4][8];
#pragma unroll
    for (int q = 0; q < 4; ++q) {
        const float* wr = Whhp + (size_t)(16 * q + l) * 16;
#pragma unroll
        for (int j = 0; j < 8; ++j) w2[q][j] = pack2(wr[2 * j], wr[2 * j + 1]);
    }
    ull h2[2][8];
    float c[2] = {0.f, 0.f};
#pragma unroll
    for (int it = 0; it < 2; ++it)
#pragma unroll
        for (int j = 0; j < 8; ++j) h2[it][j] = 0ull;
    unsigned base = lane & ~15u;
    const int TS = B_DIM * 64;
    const float* gb[2];
    float* zo[2];
#pragma unroll
    for (int it = 0; it < 2; ++it) {
        gb[it] = g_Gp + (size_t)(b0 + it) * 64 + l;
        zo[it] = g_z + (size_t)(b0 + it) * 16 + l;
    }

    float buf0[2][4], buf1[2][4];
#pragma unroll
    for (int it = 0; it < 2; ++it) {
        const float* p = gb[it];
        buf0[it][0] = p[0]; buf0[it][1] = p[16]; buf0[it][2] = p[32]; buf0[it][3] = p[48];
        p = gb[it] + TS;
        buf1[it][0] = p[0]; buf1[it][1] = p[16]; buf1[it][2] = p[32]; buf1[it][3] = p[48];
    }

    auto step = [&](float (&bf)[2][4], int t) {
        float xs[2][4];
#pragma unroll
        for (int it = 0; it < 2; ++it)
#pragma unroll
            for (int q = 0; q < 4; ++q) xs[it][q] = bf[it][q];
        if (t < 126) {                                  // prefetch t+2
#pragma unroll
            for (int it = 0; it < 2; ++it) {
                const float* p = gb[it] + (size_t)(t + 2) * TS;
                bf[it][0] = p[0]; bf[it][1] = p[16]; bf[it][2] = p[32]; bf[it][3] = p[48];
            }
        }
#pragma unroll
        for (int it = 0; it < 2; ++it)
#pragma unroll
            for (int q = 0; q < 4; ++q) {
                ull d = fmul2(h2[it][0], w2[q][0]);
#pragma unroll
                for (int j = 1; j < 8; ++j) d = ffma2(h2[it][j], w2[q][j], d);
                xs[it][q] += hsum2(d);
            }
        float hn[2];
#pragma unroll
        for (int it = 0; it < 2; ++it) {
            float iv = sigmoidf_(xs[it][0]), fv = sigmoidf_(xs[it][1]);
            float gv = tanhf_(xs[it][2]),    ov = sigmoidf_(xs[it][3]);
            c[it] = fv * c[it] + iv * gv;
            hn[it] = ov * tanhf_(c[it]);
            zo[it][(size_t)t * (B_DIM * 16)] = hn[it];
        }
#pragma unroll
        for (int j = 0; j < 8; ++j) {
            float a0 = __shfl_sync(0xffffffffu, hn[0], base + 2 * j);
            float a1 = __shfl_sync(0xffffffffu, hn[0], base + 2 * j + 1);
            float b0v = __shfl_sync(0xffffffffu, hn[1], base + 2 * j);
            float b1v = __shfl_sync(0xffffffffu, hn[1], base + 2 * j + 1);
            h2[0][j] = pack2(a0, a1);
            h2[1][j] = pack2(b0v, b1v);
        }
    };
    for (int t = 0; t < 128; t += 2) { step(buf0, t); step(buf1, t + 1); }
}

// =====================================================================
// Kernel 5: softmax denominators, 2 columns per thread.
// rs[t][c] = 1 / sum_b exp(h[t,b].z[t,c]); |attn|<=16 -> no max needed.
// =====================================================================
__global__ __launch_bounds__(128) void k_colsum()
{
    __shared__ __align__(16) float hs[512][16];
    int t = blockIdx.y, chunk = blockIdx.x, tid = threadIdx.x;
    const float4* hbase = (const float4*)(g_h + (size_t)t * B_DIM * 16);
    for (int i = tid; i < 2048; i += 128) ((float4*)hs)[i] = hbase[i];
    __syncthreads();
    int c0 = chunk * 256 + tid, c1 = c0 + 128;
    ull zA[8], zB[8];
    {
        const ull* zp = (const ull*)(g_z + ((size_t)t * B_DIM + c0) * 16);
#pragma unroll
        for (int j = 0; j < 8; ++j) zA[j] = zp[j];
        zp = (const ull*)(g_z + ((size_t)t * B_DIM + c1) * 16);
#pragma unroll
        for (int j = 0; j < 8; ++j) zB[j] = zp[j];
    }
    float sA = 0.f, sB = 0.f;
    for (int b2 = 0; b2 < 512; ++b2) {
        const ulonglong2* hp = (const ulonglong2*)hs[b2];
        ulonglong2 q0 = hp[0], q1 = hp[1], q2 = hp[2], q3 = hp[3];
        ull h0 = q0.x, h1 = q0.y, h2 = q1.x, h3 = q1.y;
        ull h4 = q2.x, h5 = q2.y, h6 = q3.x, h7 = q3.y;
        ull dA = fmul2(h0, zA[0]);
        dA = ffma2(h1, zA[1], dA); dA = ffma2(h2, zA[2], dA); dA = ffma2(h3, zA[3], dA);
        dA = ffma2(h4, zA[4], dA); dA = ffma2(h5, zA[5], dA);
        dA = ffma2(h6, zA[6], dA); dA = ffma2(h7, zA[7], dA);
        ull dB = fmul2(h0, zB[0]);
        dB = ffma2(h1, zB[1], dB); dB = ffma2(h2, zB[2], dB); dB = ffma2(h3, zB[3], dB);
        dB = ffma2(h4, zB[4], dB); dB = ffma2(h5, zB[5], dB);
        dB = ffma2(h6, zB[6], dB); dB = ffma2(h7, zB[7], dB);
        sA += ex2f(LOG2E * hsum2(dA));
        sB += ex2f(LOG2E * hsum2(dB));
    }
    g_rs[(size_t)t * B_DIM + c0] = 1.0f / sA;
    g_rs[(size_t)t * B_DIM + c1] = 1.0f / sB;
}

// =====================================================================
// Kernel 6: ctx accumulation + scoring head, 2 rows (b) per thread.
// =====================================================================
__global__ void k_ctx_out(const float* __restrict__ Wh, const float* __restrict__ We,
                          const float* __restrict__ Wv, float* __restrict__ out)
{
    extern __shared__ __align__(16) float sm[];
    float (*hs)[16] = (float(*)[16])sm;            // 8192 floats
    float (*zs)[16] = (float(*)[16])(sm + 8192);   // 8192 floats
    float* rs = sm + 16384;                        // 512
    float* wh = sm + 16896;                        // 256
    float* we = sm + 17152;                        // 256
    float* wv = sm + 17408;                        // 16
    int t = blockIdx.y, chunk = blockIdx.x, tid = threadIdx.x;
    const float4* hbase = (const float4*)(g_h + (size_t)t * B_DIM * 16);
    const float4* zbase = (const float4*)(g_z + (size_t)t * B_DIM * 16);
    for (int i = tid; i < 2048; i += 128) {
        ((float4*)hs)[i] = hbase[i];
        ((float4*)zs)[i] = zbase[i];
    }
    for (int i = tid; i < 512; i += 128) rs[i] = g_rs[(size_t)t * B_DIM + i];
    for (int i = tid; i < 256; i += 128) { wh[i] = Wh[i]; we[i] = We[i]; }
    if (tid < 16) wv[tid] = Wv[tid];
    __syncthreads();

    int b0 = chunk * 256 + tid, b1 = b0 + 128;
    ull hbA[8], hbB[8];
#pragma unroll
    for (int j = 0; j < 8; ++j) {
        hbA[j] = ((const ull*)hs[b0])[j];
        hbB[j] = ((const ull*)hs[b1])[j];
    }
    ull ctxA[8], ctxB[8];
#pragma unroll
    for (int j = 0; j < 8; ++j) { ctxA[j] = 0ull; ctxB[j] = 0ull; }

    for (int c2 = 0; c2 < 512; ++c2) {
        const ulonglong2* zp = (const ulonglong2*)zs[c2];
        ulonglong2 q0 = zp[0], q1 = zp[1], q2 = zp[2], q3 = zp[3];
        ull z0 = q0.x, z1 = q0.y, z2 = q1.x, z3 = q1.y;
        ull z4 = q2.x, z5 = q2.y, z6 = q3.x, z7 = q3.y;
        ull dA = fmul2(z0, hbA[0]);
        dA = ffma2(z1, hbA[1], dA); dA = ffma2(z2, hbA[2], dA); dA = ffma2(z3, hbA[3], dA);
        dA = ffma2(z4, hbA[4], dA); dA = ffma2(z5, hbA[5], dA);
        dA = ffma2(z6, hbA[6], dA); dA = ffma2(z7, hbA[7], dA);
        ull dB = fmul2(z0, hbB[0]);
        dB = ffma2(z1, hbB[1], dB); dB = ffma2(z2, hbB[2], dB); dB = ffma2(z3, hbB[3], dB);
        dB = ffma2(z4, hbB[4], dB); dB = ffma2(z5, hbB[5], dB);
        dB = ffma2(z6, hbB[6], dB); dB = ffma2(z7, hbB[7], dB);
        float r = rs[c2];
        float wA = ex2f(LOG2E * hsum2(dA)) * r;
        float wB = ex2f(LOG2E * hsum2(dB)) * r;
        ull wpA = pack2(wA, wA), wpB = pack2(wB, wB);
        const ulonglong2* hp = (const ulonglong2*)hs[c2];
        ulonglong2 p0 = hp[0], p1 = hp[1], p2 = hp[2], p3 = hp[3];
        ull hh[8] = {p0.x, p0.y, p1.x, p1.y, p2.x, p2.y, p3.x, p3.y};
#pragma unroll
        for (int j = 0; j < 8; ++j) {
            ctxA[j] = ffma2(wpA, hh[j], ctxA[j]);
            ctxB[j] = ffma2(wpB, hh[j], ctxB[j]);
        }
    }
    float cxA[16], cxB[16];
#pragma unroll
    for (int j = 0; j < 8; ++j) {
        unpk2(ctxA[j], cxA[2 * j], cxA[2 * j + 1]);
        unpk2(ctxB[j], cxB[2 * j], cxB[2 * j + 1]);
    }

    float pA = 0.f, pB = 0.f;
#pragma unroll
    for (int e = 0; e < 16; ++e) {
        float uA = 0.f, uB = 0.f;
#pragma unroll
        for (int d = 0; d < 16; ++d) {
            float whv = wh[e * 16 + d], wev = we[e * 16 + d];
            uA += hs[b0][d] * whv + cxA[d] * wev;
            uB += hs[b1][d] * whv + cxB[d] * wev;
        }
        pA += tanhf_(uA) * wv[e];
        pB += tanhf_(uB) * wv[e];
    }
    out[(size_t)t * B_DIM + b0] = sigmoidf_(pA);
    out[(size_t)t * B_DIM + b1] = sigmoidf_(pB);
}

// =====================================================================
extern "C" void kernel_launch(void* const* d_in, const int* in_sizes, int n_in,
                              void* d_out, int out_size)
{
    (void)in_sizes; (void)n_in; (void)out_size;
    const float* X     = (const float*)d_in[0];
    const float* Wih_f = (const float*)d_in[1];
    const float* Whh_f = (const float*)d_in[2];
    const float* bih_f = (const float*)d_in[3];
    const float* bhh_f = (const float*)d_in[4];
    const float* Wih_b = (const float*)d_in[5];
    const float* Whh_b = (const float*)d_in[6];
    const float* bih_b = (const float*)d_in[7];
    const float* bhh_b = (const float*)d_in[8];
    const float* Wih_p = (const float*)d_in[9];
    const float* Whh_p = (const float*)d_in[10];
    const float* bih_p = (const float*)d_in[11];
    const float* bhh_p = (const float*)d_in[12];
    const float* W_h   = (const float*)d_in[13];
    const float* W_e   = (const float*)d_in[14];
    const float* W_v   = (const float*)d_in[15];
    float* out = (float*)d_out;

    k_gemm_in<<<512, 128>>>(X, Wih_f, Wih_b, bih_f, bhh_f, bih_b, bhh_b);
    k_bilstm<<<128, 32>>>(Whh_f, Whh_b);
    k_gp<<<TB / 4, 256>>>(Wih_p, bih_p, bhh_p);
    k_ptr<<<128, 32>>>(Whh_p);
    k_colsum<<<dim3(2, T_DIM), 128>>>();
    cudaFuncSetAttribute(k_ctx_out, cudaFuncAttributeMaxDynamicSharedMemorySize, 69696);
    k_ctx_out<<<dim3(2, T_DIM), 128, 69696>>>(W_h, W_e, W_v, out);
}

// round 11
// speedup vs baseline: 1.3381x; 1.0247x over previous
#include <cuda_runtime.h>

typedef unsigned long long ull;

#define T_DIM 128
#define B_DIM 512
#define D_IN  768
#define TB    (T_DIM * B_DIM)   // 65536
#define LOG2E 1.4426950408889634f

// ---------------- scratch (device globals; no allocations) ----------------
// g_G : [b][dir][t][32]  (scan-major for the bi-LSTM)
// g_Gp: [b][t][64]       (scan-major for the ptr-LSTM)
__device__ float g_G [TB * 64];
__device__ float g_h [TB * 16];   // [t][b][16]
__device__ float g_Gp[TB * 64];
__device__ float g_z [TB * 16];   // [t][b][16]
__device__ float g_rs[TB];        // [t][c]

// ---------------- fast activations ----------------
__device__ __forceinline__ float ex2f(float x) { float y; asm("ex2.approx.ftz.f32 %0, %1;" : "=f"(y) : "f"(x)); return y; }
__device__ __forceinline__ float rcpf(float x) { float y; asm("rcp.approx.ftz.f32 %0, %1;" : "=f"(y) : "f"(x)); return y; }
__device__ __forceinline__ float sigmoidf_(float x) { return rcpf(1.f + ex2f(-LOG2E * x)); }
__device__ __forceinline__ float tanhf_(float x)    { return 2.f * sigmoidf_(2.f * x) - 1.f; }

// ---------------- packed f32x2 helpers (sm_100+) ----------------
__device__ __forceinline__ ull ffma2(ull a, ull b, ull c) {
    ull d; asm("fma.rn.f32x2 %0, %1, %2, %3;" : "=l"(d) : "l"(a), "l"(b), "l"(c)); return d;
}
__device__ __forceinline__ ull fmul2(ull a, ull b) {
    ull d; asm("mul.rn.f32x2 %0, %1, %2;" : "=l"(d) : "l"(a), "l"(b)); return d;
}
__device__ __forceinline__ ull pack2(float x, float y) {
    ull d; asm("mov.b64 %0, {%1, %2};" : "=l"(d) : "f"(x), "f"(y)); return d;
}
__device__ __forceinline__ void unpk2(ull d, float& x, float& y) {
    asm("mov.b64 {%0, %1}, %2;" : "=f"(x), "=f"(y) : "l"(d));
}
__device__ __forceinline__ float hsum2(ull d) { float x, y; unpk2(d, x, y); return x + y; }

// =====================================================================
// Kernel 1: input GEMM  G[m][n] = X[m][:] . W2[n][:] + bias[n]
//   M=65536, N=64 (0..31 = Wih_f rows, 32..63 = Wih_b rows), K=768
//   Stores into scan-major g_G[b][dir][t][32].
// =====================================================================
__global__ __launch_bounds__(128) void k_gemm_in(
    const float* __restrict__ X,
    const float* __restrict__ Wf, const float* __restrict__ Wb,
    const float* __restrict__ bihf, const float* __restrict__ bhhf,
    const float* __restrict__ bihb, const float* __restrict__ bhhb)
{
    __shared__ __align__(16) float At[32][132];   // [k][m], pad -> conflict-free
    __shared__ __align__(16) ull   Bs2[32][66];   // [k][n] as (b,b) pairs
    int tid = threadIdx.x;
    int m0  = blockIdx.x * 128;
    int tx  = tid & 15, ty = tid >> 4;   // tx: n-group of 4, ty: m-group of 16
    ull acc[8][4];
#pragma unroll
    for (int p = 0; p < 8; ++p)
#pragma unroll
        for (int n = 0; n < 4; ++n) acc[p][n] = 0ull;

    for (int k0 = 0; k0 < D_IN; k0 += 32) {
#pragma unroll
        for (int i = 0; i < 8; ++i) {            // A tile: transpose into At
            int idx = tid + i * 128;
            int m = idx >> 3, kk = (idx & 7) << 2;
            float4 v = *(const float4*)(X + (size_t)(m0 + m) * D_IN + k0 + kk);
            At[kk + 0][m] = v.x; At[kk + 1][m] = v.y; At[kk + 2][m] = v.z; At[kk + 3][m] = v.w;
        }
#pragma unroll
        for (int i = 0; i < 4; ++i) {            // B tile -> duplicated pairs
            int idx = tid + i * 128;
            int n = idx >> 3, kk = (idx & 7) << 2;
            const float* src = (n < 32) ? (Wf + (size_t)n * D_IN) : (Wb + (size_t)(n - 32) * D_IN);
            float4 v = *(const float4*)(src + k0 + kk);
            Bs2[kk + 0][n] = pack2(v.x, v.x); Bs2[kk + 1][n] = pack2(v.y, v.y);
            Bs2[kk + 2][n] = pack2(v.z, v.z); Bs2[kk + 3][n] = pack2(v.w, v.w);
        }
        __syncthreads();
#pragma unroll
        for (int k = 0; k < 32; ++k) {
            const ulonglong2* ap = (const ulonglong2*)&At[k][ty * 16];
            ulonglong2 a01 = ap[0], a23 = ap[1], a45 = ap[2], a67 = ap[3];
            ull a[8] = {a01.x, a01.y, a23.x, a23.y, a45.x, a45.y, a67.x, a67.y};
            const ulonglong2* bp = (const ulonglong2*)&Bs2[k][tx * 4];
            ulonglong2 b01 = bp[0], b23 = bp[1];
            ull bb[4] = {b01.x, b01.y, b23.x, b23.y};
#pragma unroll
            for (int p = 0; p < 8; ++p)
#pragma unroll
                for (int n = 0; n < 4; ++n) acc[p][n] = ffma2(a[p], bb[n], acc[p][n]);
        }
        __syncthreads();
    }
    float bias[4];
#pragma unroll
    for (int n = 0; n < 4; ++n) {
        int nn = tx * 4 + n;
        bias[n] = (nn < 32) ? (bihf[nn] + bhhf[nn]) : (bihb[nn - 32] + bhhb[nn - 32]);
    }
    int nbase = tx * 4;            // 0..60, multiple of 4
    int dirv  = nbase >> 5;        // 0 or 1
    int off   = nbase & 31;        // gate offset within 32
#pragma unroll
    for (int p = 0; p < 8; ++p) {
        float lo[4], hi[4];
#pragma unroll
        for (int n = 0; n < 4; ++n) unpk2(acc[p][n], lo[n], hi[n]);
        int m = m0 + ty * 16 + 2 * p;
        int t0 = m >> 9, b0 = m & 511;
        int t1 = (m + 1) >> 9, b1 = (m + 1) & 511;
        *(float4*)(g_G + (size_t)b0 * 8192 + dirv * 4096 + t0 * 32 + off) =
            make_float4(lo[0] + bias[0], lo[1] + bias[1], lo[2] + bias[2], lo[3] + bias[3]);
        *(float4*)(g_G + (size_t)b1 * 8192 + dirv * 4096 + t1 * 32 + off) =
            make_float4(hi[0] + bias[0], hi[1] + bias[1], hi[2] + bias[2], hi[3] + bias[3]);
    }
}

// =====================================================================
// Kernel 2: bi-LSTM scan. 8 lanes per (item,dir); lane l owns hidden
// unit l. Single chain per thread; 2 warps/block; gates streamed from
// scan-major g_G (contiguous in t). Distance-2 prefetch.
// =====================================================================
__global__ __launch_bounds__(64) void k_bilstm(const float* __restrict__ WhhF,
                                               const float* __restrict__ WhhB)
{
    int tid  = threadIdx.x;
    int lane = tid & 31, wid = tid >> 5;
    int l = lane & 7;
    int p = (blockIdx.x * 2 + wid) * 4 + (lane >> 3);   // chain 0..1023
    int dir = p >> 9;
    int b = p & 511;
    const float* Whh = dir ? WhhB : WhhF;
    ull w2[4][4];
#pragma unroll
    for (int q = 0; q < 4; ++q) {
        const float* wr = Whh + (size_t)(8 * q + l) * 8;
#pragma unroll
        for (int j = 0; j < 4; ++j) w2[q][j] = pack2(wr[2 * j], wr[2 * j + 1]);
    }
    ull h2[4] = {0ull, 0ull, 0ull, 0ull};
    float c = 0.f;
    unsigned base = lane & ~7u;
    const float* gbase = g_G + (size_t)b * 8192 + dir * 4096 + l;   // + t*32 + 8q
    float* hout = g_h + (size_t)b * 16 + dir * 8 + l;               // + t*8192

    float buf0[4], buf1[4];
    {
        const float* pp = gbase + (size_t)(dir ? 127 : 0) * 32;
        buf0[0] = pp[0]; buf0[1] = pp[8]; buf0[2] = pp[16]; buf0[3] = pp[24];
        pp = gbase + (size_t)(dir ? 126 : 1) * 32;
        buf1[0] = pp[0]; buf1[1] = pp[8]; buf1[2] = pp[16]; buf1[3] = pp[24];
    }

    auto step = [&](float* bf, int s) {
        float xs[4] = {bf[0], bf[1], bf[2], bf[3]};
        if (s < 126) {                                    // prefetch s+2
            int tn = dir ? (125 - s) : (s + 2);
            const float* pp = gbase + (size_t)tn * 32;
            bf[0] = pp[0]; bf[1] = pp[8]; bf[2] = pp[16]; bf[3] = pp[24];
        }
#pragma unroll
        for (int q = 0; q < 4; ++q) {
            ull d = fmul2(h2[0], w2[q][0]);
            d = ffma2(h2[1], w2[q][1], d);
            d = ffma2(h2[2], w2[q][2], d);
            d = ffma2(h2[3], w2[q][3], d);
            xs[q] += hsum2(d);
        }
        float iv = sigmoidf_(xs[0]), fv = sigmoidf_(xs[1]);
        float gv = tanhf_(xs[2]),    ov = sigmoidf_(xs[3]);
        c = fv * c + iv * gv;
        float hn = ov * tanhf_(c);
        int t = dir ? (127 - s) : s;
        hout[(size_t)t * (B_DIM * 16)] = hn;
#pragma unroll
        for (int j = 0; j < 4; ++j) {
            float a0 = __shfl_sync(0xffffffffu, hn, base + 2 * j);
            float a1 = __shfl_sync(0xffffffffu, hn, base + 2 * j + 1);
            h2[j] = pack2(a0, a1);
        }
    };
    for (int s = 0; s < 128; s += 2) { step(buf0, s); step(buf1, s + 1); }
}

// =====================================================================
// Kernel 3: ptr-LSTM input projection into scan-major g_Gp[b][t][64]
// =====================================================================
__global__ __launch_bounds__(256) void k_gp(const float* __restrict__ Wihp,
                                            const float* __restrict__ bihp,
                                            const float* __restrict__ bhhp)
{
    __shared__ float Wp[64][17];
    __shared__ float bs[64];
    int tid = threadIdx.x;
    if (tid < 64) bs[tid] = bihp[tid] + bhhp[tid];
    for (int i = tid; i < 1024; i += 256) Wp[i >> 4][i & 15] = Wihp[i];
    __syncthreads();
    int n  = tid & 63, mi = tid >> 6;
    int m  = blockIdx.x * 4 + mi;
    int t = m >> 9, b = m & 511;
    const float* hr = g_h + (size_t)m * 16;
    float4 h0 = *(const float4*)hr,       h1 = *(const float4*)(hr + 4);
    float4 h2 = *(const float4*)(hr + 8), h3 = *(const float4*)(hr + 12);
    float hv[16] = {h0.x, h0.y, h0.z, h0.w, h1.x, h1.y, h1.z, h1.w,
                    h2.x, h2.y, h2.z, h2.w, h3.x, h3.y, h3.z, h3.w};
    float acc = bs[n];
#pragma unroll
    for (int k = 0; k < 16; ++k) acc += hv[k] * Wp[n][k];
    g_Gp[(size_t)b * 8192 + t * 64 + n] = acc;
}

// =====================================================================
// Kernel 4: ptr-LSTM scan. 16 lanes/item; lane l owns hidden unit l.
// Single chain per thread; 2 warps/block; scan-major streaming loads.
// =====================================================================
__global__ __launch_bounds__(64) void k_ptr(const float* __restrict__ Whhp)
{
    int tid  = threadIdx.x;
    int lane = tid & 31, wid = tid >> 5;
    int l = lane & 15;
    int b = (blockIdx.x * 2 + wid) * 2 + (lane >> 4);   // item 0..511
    ull w2[4][8];
#pragma unroll
    for (int q = 0; q < 4; ++q) {
        const float* wr = Whhp + (size_t)(16 * q + l) * 16;
#pragma unroll
        for (int j = 0; j < 8; ++j) w2[q][j] = pack2(wr[2 * j], wr[2 * j + 1]);
    }
    ull h2[8];
#pragma unroll
    for (int j = 0; j < 8; ++j) h2[j] = 0ull;
    float c = 0.f;
    unsigned base = lane & ~15u;
    const float* gbase = g_Gp + (size_t)b * 8192 + l;   // + t*64 + 16q
    float* zout = g_z + (size_t)b * 16 + l;             // + t*8192

    float buf0[4], buf1[4];
    {
        const float* pp = gbase;
        buf0[0] = pp[0]; buf0[1] = pp[16]; buf0[2] = pp[32]; buf0[3] = pp[48];
        pp = gbase + 64;
        buf1[0] = pp[0]; buf1[1] = pp[16]; buf1[2] = pp[32]; buf1[3] = pp[48];
    }

    auto step = [&](float* bf, int t) {
        float xs[4] = {bf[0], bf[1], bf[2], bf[3]};
        if (t < 126) {                                  // prefetch t+2
            const float* pp = gbase + (size_t)(t + 2) * 64;
            bf[0] = pp[0]; bf[1] = pp[16]; bf[2] = pp[32]; bf[3] = pp[48];
        }
#pragma unroll
        for (int q = 0; q < 4; ++q) {
            ull d = fmul2(h2[0], w2[q][0]);
#pragma unroll
            for (int j = 1; j < 8; ++j) d = ffma2(h2[j], w2[q][j], d);
            xs[q] += hsum2(d);
        }
        float iv = sigmoidf_(xs[0]), fv = sigmoidf_(xs[1]);
        float gv = tanhf_(xs[2]),    ov = sigmoidf_(xs[3]);
        c = fv * c + iv * gv;
        float hn = ov * tanhf_(c);
        zout[(size_t)t * (B_DIM * 16)] = hn;
#pragma unroll
        for (int j = 0; j < 8; ++j) {
            float a0 = __shfl_sync(0xffffffffu, hn, base + 2 * j);
            float a1 = __shfl_sync(0xffffffffu, hn, base + 2 * j + 1);
            h2[j] = pack2(a0, a1);
        }
    };
    for (int t = 0; t < 128; t += 2) { step(buf0, t); step(buf1, t + 1); }
}

// =====================================================================
// Kernel 5: softmax denominators, 2 columns per thread.
// rs[t][c] = 1 / sum_b exp(h[t,b].z[t,c]); |attn|<=16 -> no max needed.
// =====================================================================
__global__ __launch_bounds__(128) void k_colsum()
{
    __shared__ __align__(16) float hs[512][16];
    int t = blockIdx.y, chunk = blockIdx.x, tid = threadIdx.x;
    const float4* hbase = (const float4*)(g_h + (size_t)t * B_DIM * 16);
    for (int i = tid; i < 2048; i += 128) ((float4*)hs)[i] = hbase[i];
    __syncthreads();
    int c0 = chunk * 256 + tid, c1 = c0 + 128;
    ull zA[8], zB[8];
    {
        const ull* zp = (const ull*)(g_z + ((size_t)t * B_DIM + c0) * 16);
#pragma unroll
        for (int j = 0; j < 8; ++j) zA[j] = zp[j];
        zp = (const ull*)(g_z + ((size_t)t * B_DIM + c1) * 16);
#pragma unroll
        for (int j = 0; j < 8; ++j) zB[j] = zp[j];
    }
    float sA = 0.f, sB = 0.f;
    for (int b2 = 0; b2 < 512; ++b2) {
        const ulonglong2* hp = (const ulonglong2*)hs[b2];
        ulonglong2 q0 = hp[0], q1 = hp[1], q2 = hp[2], q3 = hp[3];
        ull h0 = q0.x, h1 = q0.y, h2 = q1.x, h3 = q1.y;
        ull h4 = q2.x, h5 = q2.y, h6 = q3.x, h7 = q3.y;
        ull dA = fmul2(h0, zA[0]);
        dA = ffma2(h1, zA[1], dA); dA = ffma2(h2, zA[2], dA); dA = ffma2(h3, zA[3], dA);
        dA = ffma2(h4, zA[4], dA); dA = ffma2(h5, zA[5], dA);
        dA = ffma2(h6, zA[6], dA); dA = ffma2(h7, zA[7], dA);
        ull dB = fmul2(h0, zB[0]);
        dB = ffma2(h1, zB[1], dB); dB = ffma2(h2, zB[2], dB); dB = ffma2(h3, zB[3], dB);
        dB = ffma2(h4, zB[4], dB); dB = ffma2(h5, zB[5], dB);
        dB = ffma2(h6, zB[6], dB); dB = ffma2(h7, zB[7], dB);
        sA += ex2f(LOG2E * hsum2(dA));
        sB += ex2f(LOG2E * hsum2(dB));
    }
    g_rs[(size_t)t * B_DIM + c0] = 1.0f / sA;
    g_rs[(size_t)t * B_DIM + c1] = 1.0f / sB;
}

// =====================================================================
// Kernel 6: ctx accumulation + scoring head, 2 rows (b) per thread.
// =====================================================================
__global__ void k_ctx_out(const float* __restrict__ Wh, const float* __restrict__ We,
                          const float* __restrict__ Wv, float* __restrict__ out)
{
    extern __shared__ __align__(16) float sm[];
    float (*hs)[16] = (float(*)[16])sm;            // 8192 floats
    float (*zs)[16] = (float(*)[16])(sm + 8192);   // 8192 floats
    float* rs = sm + 16384;                        // 512
    float* wh = sm + 16896;                        // 256
    float* we = sm + 17152;                        // 256
    float* wv = sm + 17408;                        // 16
    int t = blockIdx.y, chunk = blockIdx.x, tid = threadIdx.x;
    const float4* hbase = (const float4*)(g_h + (size_t)t * B_DIM * 16);
    const float4* zbase = (const float4*)(g_z + (size_t)t * B_DIM * 16);
    for (int i = tid; i < 2048; i += 128) {
        ((float4*)hs)[i] = hbase[i];
        ((float4*)zs)[i] = zbase[i];
    }
    for (int i = tid; i < 512; i += 128) rs[i] = g_rs[(size_t)t * B_DIM + i];
    for (int i = tid; i < 256; i += 128) { wh[i] = Wh[i]; we[i] = We[i]; }
    if (tid < 16) wv[tid] = Wv[tid];
    __syncthreads();

    int b0 = chunk * 256 + tid, b1 = b0 + 128;
    ull hbA[8], hbB[8];
#pragma unroll
    for (int j = 0; j < 8; ++j) {
        hbA[j] = ((const ull*)hs[b0])[j];
        hbB[j] = ((const ull*)hs[b1])[j];
    }
    ull ctxA[8], ctxB[8];
#pragma unroll
    for (int j = 0; j < 8; ++j) { ctxA[j] = 0ull; ctxB[j] = 0ull; }

    for (int c2 = 0; c2 < 512; ++c2) {
        const ulonglong2* zp = (const ulonglong2*)zs[c2];
        ulonglong2 q0 = zp[0], q1 = zp[1], q2 = zp[2], q3 = zp[3];
        ull z0 = q0.x, z1 = q0.y, z2 = q1.x, z3 = q1.y;
        ull z4 = q2.x, z5 = q2.y, z6 = q3.x, z7 = q3.y;
        ull dA = fmul2(z0, hbA[0]);
        dA = ffma2(z1, hbA[1], dA); dA = ffma2(z2, hbA[2], dA); dA = ffma2(z3, hbA[3], dA);
        dA = ffma2(z4, hbA[4], dA); dA = ffma2(z5, hbA[5], dA);
        dA = ffma2(z6, hbA[6], dA); dA = ffma2(z7, hbA[7], dA);
        ull dB = fmul2(z0, hbB[0]);
        dB = ffma2(z1, hbB[1], dB); dB = ffma2(z2, hbB[2], dB); dB = ffma2(z3, hbB[3], dB);
        dB = ffma2(z4, hbB[4], dB); dB = ffma2(z5, hbB[5], dB);
        dB = ffma2(z6, hbB[6], dB); dB = ffma2(z7, hbB[7], dB);
        float r = rs[c2];
        float wA = ex2f(LOG2E * hsum2(dA)) * r;
        float wB = ex2f(LOG2E * hsum2(dB)) * r;
        ull wpA = pack2(wA, wA), wpB = pack2(wB, wB);
        const ulonglong2* hp = (const ulonglong2*)hs[c2];
        ulonglong2 p0 = hp[0], p1 = hp[1], p2 = hp[2], p3 = hp[3];
        ull hh[8] = {p0.x, p0.y, p1.x, p1.y, p2.x, p2.y, p3.x, p3.y};
#pragma unroll
        for (int j = 0; j < 8; ++j) {
            ctxA[j] = ffma2(wpA, hh[j], ctxA[j]);
            ctxB[j] = ffma2(wpB, hh[j], ctxB[j]);
        }
    }
    float cxA[16], cxB[16];
#pragma unroll
    for (int j = 0; j < 8; ++j) {
        unpk2(ctxA[j], cxA[2 * j], cxA[2 * j + 1]);
        unpk2(ctxB[j], cxB[2 * j], cxB[2 * j + 1]);
    }

    float pA = 0.f, pB = 0.f;
#pragma unroll
    for (int e = 0; e < 16; ++e) {
        float uA = 0.f, uB = 0.f;
#pragma unroll
        for (int d = 0; d < 16; ++d) {
            float whv = wh[e * 16 + d], wev = we[e * 16 + d];
            uA += hs[b0][d] * whv + cxA[d] * wev;
            uB += hs[b1][d] * whv + cxB[d] * wev;
        }
        pA += tanhf_(uA) * wv[e];
        pB += tanhf_(uB) * wv[e];
    }
    out[(size_t)t * B_DIM + b0] = sigmoidf_(pA);
    out[(size_t)t * B_DIM + b1] = sigmoidf_(pB);
}

// =====================================================================
extern "C" void kernel_launch(void* const* d_in, const int* in_sizes, int n_in,
                              void* d_out, int out_size)
{
    (void)in_sizes; (void)n_in; (void)out_size;
    const float* X     = (const float*)d_in[0];
    const float* Wih_f = (const float*)d_in[1];
    const float* Whh_f = (const float*)d_in[2];
    const float* bih_f = (const float*)d_in[3];
    const float* bhh_f = (const float*)d_in[4];
    const float* Wih_b = (const float*)d_in[5];
    const float* Whh_b = (const float*)d_in[6];
    const float* bih_b = (const float*)d_in[7];
    const float* bhh_b = (const float*)d_in[8];
    const float* Wih_p = (const float*)d_in[9];
    const float* Whh_p = (const float*)d_in[10];
    const float* bih_p = (const float*)d_in[11];
    const float* bhh_p = (const float*)d_in[12];
    const float* W_h   = (const float*)d_in[13];
    const float* W_e   = (const float*)d_in[14];
    const float* W_v   = (const float*)d_in[15];
    float* out = (float*)d_out;

    k_gemm_in<<<512, 128>>>(X, Wih_f, Wih_b, bih_f, bhh_f, bih_b, bhh_b);
    k_bilstm<<<128, 64>>>(Whh_f, Whh_b);
    k_gp<<<TB / 4, 256>>>(Wih_p, bih_p, bhh_p);
    k_ptr<<<128, 64>>>(Whh_p);
    k_colsum<<<dim3(2, T_DIM), 128>>>();
    cudaFuncSetAttribute(k_ctx_out, cudaFuncAttributeMaxDynamicSharedMemorySize, 69696);
    k_ctx_out<<<dim3(2, T_DIM), 128, 69696>>>(W_h, W_e, W_v, out);
}